// round 1
// baseline (speedup 1.0000x reference)
#include <cuda_runtime.h>
#include <math.h>

#define HH 128
#define WW 128
#define NB 4

// Scratch (static __device__ arrays — no allocation in kernel_launch).
__device__ float g_bufA[NB * 64 * HH * WW];    // 16 MB
__device__ float g_bufB[NB * 64 * HH * WW];    // 16 MB
__device__ float g_offb[NB * 144 * HH * WW];   // 37.75 MB
__device__ float g_wt[576 * 64];               // transposed deform weights

// ---------------------------------------------------------------------------
// 3x3 conv, stride 1, pad 1, NCHW. Tile: 32 wide x 16 tall, 16 output
// channels per block. 256 threads; each thread computes 4 oc x 8 px.
// For C_IN==128 the input is the channel-concat of in0 (ch 0..63) and
// in1 (ch 64..127); both tensors individually have 64 channels.
// ---------------------------------------------------------------------------
template <int C_IN, int C_OUT>
__global__ __launch_bounds__(256, 3)
void conv3x3_kernel(const float* __restrict__ in0, const float* __restrict__ in1,
                    const float* __restrict__ w, const float* __restrict__ bias,
                    float* __restrict__ out)
{
    __shared__ __align__(16) float s_in[18 * 36];   // 18 rows x 34 cols used, stride 36
    __shared__ float s_w[16 * 9];

    const int tid = threadIdx.x;
    const int bx0 = blockIdx.x * 32;
    const int by0 = blockIdx.y * 16;
    const int z   = blockIdx.z;
    const int b   = z / (C_OUT / 16);
    const int ocb = (z % (C_OUT / 16)) * 16;

    const int pg  = tid & 63;           // 64 pixel-groups of 8 horizontal px
    const int row = pg >> 2;            // 0..15
    const int xq  = (pg & 3) * 8;       // 0,8,16,24
    const int ocg = tid >> 6;           // 0..3 -> 4 oc each

    float acc[4][8];
#pragma unroll
    for (int o = 0; o < 4; o++)
#pragma unroll
        for (int p = 0; p < 8; p++) acc[o][p] = 0.0f;

    for (int ic = 0; ic < C_IN; ic++) {
        const float* src = (ic < 64) ? in0 : in1;
        const int icl = ic & 63;
        const float* inp = src + ((size_t)b * 64 + icl) * (HH * WW);

        // cooperative halo-tile load: 18 x 34 region
#pragma unroll
        for (int e = tid; e < 18 * 34; e += 256) {
            int r = e / 34;
            int c = e - r * 34;
            int gy = by0 + r - 1;
            int gx = bx0 + c - 1;
            float v = 0.0f;
            if (gy >= 0 && gy < HH && gx >= 0 && gx < WW)
                v = inp[gy * WW + gx];
            s_in[r * 36 + c] = v;
        }
        if (tid < 144)
            s_w[tid] = w[((size_t)(ocb + tid / 9) * C_IN + ic) * 9 + (tid % 9)];
        __syncthreads();

#pragma unroll
        for (int ky = 0; ky < 3; ky++) {
            const float* sr = &s_in[(row + ky) * 36 + xq];
            float4 a  = *(const float4*)(sr);
            float4 bb = *(const float4*)(sr + 4);
            float2 cc = *(const float2*)(sr + 8);
            float v[10] = {a.x, a.y, a.z, a.w, bb.x, bb.y, bb.z, bb.w, cc.x, cc.y};
#pragma unroll
            for (int kx = 0; kx < 3; kx++) {
                const int widx = ky * 3 + kx;
                float w0 = s_w[(ocg * 4 + 0) * 9 + widx];
                float w1 = s_w[(ocg * 4 + 1) * 9 + widx];
                float w2 = s_w[(ocg * 4 + 2) * 9 + widx];
                float w3 = s_w[(ocg * 4 + 3) * 9 + widx];
#pragma unroll
                for (int p = 0; p < 8; p++) {
                    float vv = v[kx + p];
                    acc[0][p] += vv * w0;
                    acc[1][p] += vv * w1;
                    acc[2][p] += vv * w2;
                    acc[3][p] += vv * w3;
                }
            }
        }
        __syncthreads();
    }

    const int y  = by0 + row;
    const int x0 = bx0 + xq;
#pragma unroll
    for (int o = 0; o < 4; o++) {
        int oc = ocb + ocg * 4 + o;
        float bv = bias[oc];
        float4 r0, r1;
        r0.x = acc[o][0] + bv; r0.y = acc[o][1] + bv;
        r0.z = acc[o][2] + bv; r0.w = acc[o][3] + bv;
        r1.x = acc[o][4] + bv; r1.y = acc[o][5] + bv;
        r1.z = acc[o][6] + bv; r1.w = acc[o][7] + bv;
        float* op = &out[(((size_t)b * C_OUT + oc) * HH + y) * WW + x0];
        *(float4*)(op)     = r0;
        *(float4*)(op + 4) = r1;
    }
}

// ---------------------------------------------------------------------------
// transpose deform weights w[64][64*9] -> wt[576][64]
// ---------------------------------------------------------------------------
__global__ void transpose_w_kernel(const float* __restrict__ w, float* __restrict__ wt)
{
    int i = blockIdx.x * 256 + threadIdx.x;
    if (i < 64 * 576) {
        int oc = i / 576;
        int kk = i - oc * 576;
        wt[kk * 64 + oc] = w[i];
    }
}

// ---------------------------------------------------------------------------
// Deformable conv. Block: 8x8 spatial tile, all 64 oc, one batch.
// Per DG-pair chunk: stage bilinear-sampled cols (144 x 64 px) in smem,
// then register-tiled GEMM (each thread: 4 oc x 4 px).
// ---------------------------------------------------------------------------
__global__ __launch_bounds__(256, 3)
void deform_kernel(const float* __restrict__ x, const float* __restrict__ off,
                   const float* __restrict__ wt, const float* __restrict__ bias,
                   float* __restrict__ out)
{
    __shared__ __align__(16) float s_cols[144 * 64];   // 36 KB

    const int tid = threadIdx.x;
    const int b   = blockIdx.z;
    const int bx0 = blockIdx.x * 8;
    const int by0 = blockIdx.y * 8;

    const int pxg = tid & 15;    // 16 groups of 4 px
    const int ocg = tid >> 4;    // 16 groups of 4 oc

    float acc[4][4];
#pragma unroll
    for (int o = 0; o < 4; o++)
#pragma unroll
        for (int p = 0; p < 4; p++) acc[o][p] = 0.0f;

    for (int dgc = 0; dgc < 4; dgc++) {
        // ------- phase 1: fill cols for deform-groups {2*dgc, 2*dgc+1} -------
        for (int t = tid; t < 1152; t += 256) {
            int px   = t & 63;
            int rest = t >> 6;          // 0..17
            int k    = rest % 9;
            int dgl  = rest / 9;        // 0..1
            int dg   = dgc * 2 + dgl;

            int yy = by0 + (px >> 3);
            int xx = bx0 + (px & 7);

            int offch = (dg * 9 + k) * 2;
            size_t obase = (((size_t)b * 144 + offch) * HH + yy) * WW + xx;
            float dy = off[obase];
            float dx = off[obase + (size_t)HH * WW];

            float py  = dy + (float)yy + (float)(k / 3 - 1);
            float pxc = dx + (float)xx + (float)(k % 3 - 1);
            float y0f = floorf(py);
            float x0f = floorf(pxc);
            float wy = py - y0f;
            float wx = pxc - x0f;
            int y0 = (int)y0f;
            int x0 = (int)x0f;

            float w00 = (1.0f - wy) * (1.0f - wx);
            float w01 = (1.0f - wy) * wx;
            float w10 = wy * (1.0f - wx);
            float w11 = wy * wx;

            bool vy0 = ((unsigned)y0 < (unsigned)HH);
            bool vy1 = ((unsigned)(y0 + 1) < (unsigned)HH);
            bool vx0 = ((unsigned)x0 < (unsigned)WW);
            bool vx1 = ((unsigned)(x0 + 1) < (unsigned)WW);
            w00 *= (float)(vy0 && vx0);
            w01 *= (float)(vy0 && vx1);
            w10 *= (float)(vy1 && vx0);
            w11 *= (float)(vy1 && vx1);

            int y0c = min(max(y0, 0), HH - 1);
            int y1c = min(max(y0 + 1, 0), HH - 1);
            int x0c = min(max(x0, 0), WW - 1);
            int x1c = min(max(x0 + 1, 0), WW - 1);

            const float* base = x + ((size_t)b * 64 + dg * 8) * (HH * WW);
            int i00 = y0c * WW + x0c;
            int i01 = y0c * WW + x1c;
            int i10 = y1c * WW + x0c;
            int i11 = y1c * WW + x1c;

            int colbase = dgl * (8 * 9 * 64) + k * 64 + px;
#pragma unroll
            for (int c = 0; c < 8; c++) {
                const float* p = base + c * (HH * WW);
                float v = w00 * p[i00] + w01 * p[i01] + w10 * p[i10] + w11 * p[i11];
                s_cols[colbase + c * (9 * 64)] = v;
            }
        }
        __syncthreads();

        // ------- phase 2: partial GEMM over 144 kk -------
        const int kk0 = dgc * 144;
#pragma unroll 4
        for (int kk = 0; kk < 144; kk++) {
            float4 c4 = *(const float4*)&s_cols[kk * 64 + pxg * 4];
            float4 w4 = __ldg((const float4*)&wt[(size_t)(kk0 + kk) * 64 + ocg * 4]);
            acc[0][0] += w4.x * c4.x; acc[0][1] += w4.x * c4.y;
            acc[0][2] += w4.x * c4.z; acc[0][3] += w4.x * c4.w;
            acc[1][0] += w4.y * c4.x; acc[1][1] += w4.y * c4.y;
            acc[1][2] += w4.y * c4.z; acc[1][3] += w4.y * c4.w;
            acc[2][0] += w4.z * c4.x; acc[2][1] += w4.z * c4.y;
            acc[2][2] += w4.z * c4.z; acc[2][3] += w4.z * c4.w;
            acc[3][0] += w4.w * c4.x; acc[3][1] += w4.w * c4.y;
            acc[3][2] += w4.w * c4.z; acc[3][3] += w4.w * c4.w;
        }
        __syncthreads();
    }

    // store: px = pxg*4 .. pxg*4+3 (contiguous x within a row of the 8x8 tile)
    const int y  = by0 + (pxg >> 1);
    const int x0 = bx0 + (pxg & 1) * 4;
#pragma unroll
    for (int o = 0; o < 4; o++) {
        int oc = ocg * 4 + o;
        float bv = bias[oc];
        float4 r;
        r.x = acc[o][0] + bv; r.y = acc[o][1] + bv;
        r.z = acc[o][2] + bv; r.w = acc[o][3] + bv;
        *(float4*)&out[(((size_t)b * 64 + oc) * HH + y) * WW + x0] = r;
    }
}

// ---------------------------------------------------------------------------
extern "C" void kernel_launch(void* const* d_in, const int* in_sizes, int n_in,
                              void* d_out, int out_size)
{
    const float* neibor = (const float*)d_in[0];
    const float* target = (const float*)d_in[1];
    const float* cr_w   = (const float*)d_in[2];
    const float* cr_b   = (const float*)d_in[3];
    const float* off1_w = (const float*)d_in[4];
    const float* off1_b = (const float*)d_in[5];
    const float* d1_w   = (const float*)d_in[6];
    const float* d1_b   = (const float*)d_in[7];
    const float* off2_w = (const float*)d_in[8];
    const float* off2_b = (const float*)d_in[9];
    const float* d2_w   = (const float*)d_in[10];
    const float* d2_b   = (const float*)d_in[11];
    const float* off3_w = (const float*)d_in[12];
    const float* off3_b = (const float*)d_in[13];
    const float* d3_w   = (const float*)d_in[14];
    const float* d3_b   = (const float*)d_in[15];
    const float* off4_w = (const float*)d_in[16];
    const float* off4_b = (const float*)d_in[17];
    const float* d4_w   = (const float*)d_in[18];
    const float* d4_b   = (const float*)d_in[19];
    float* out = (float*)d_out;

    float *bufA, *bufB, *offb, *wt;
    cudaGetSymbolAddress((void**)&bufA, g_bufA);
    cudaGetSymbolAddress((void**)&bufB, g_bufB);
    cudaGetSymbolAddress((void**)&offb, g_offb);
    cudaGetSymbolAddress((void**)&wt,   g_wt);

    dim3 cb(256);
    dim3 cg64(WW / 32, HH / 16, NB * (64 / 16));    // (4, 8, 16)
    dim3 cg144(WW / 32, HH / 16, NB * (144 / 16));  // (4, 8, 36)
    dim3 dg(WW / 8, HH / 8, NB);                    // (16, 16, 4)

    // 1. fea = conv(concat(neibor, target))            -> bufA
    conv3x3_kernel<128, 64><<<cg64, cb>>>(neibor, target, cr_w, cr_b, bufA);
    // 2. o1 = conv(fea)                                -> offb
    conv3x3_kernel<64, 144><<<cg144, cb>>>(bufA, bufA, off1_w, off1_b, offb);
    // 3. fea = deform(fea, o1)                         -> bufB
    transpose_w_kernel<<<144, 256>>>(d1_w, wt);
    deform_kernel<<<dg, cb>>>(bufA, offb, wt, d1_b, bufB);
    // 4. o2 = conv(fea)
    conv3x3_kernel<64, 144><<<cg144, cb>>>(bufB, bufB, off2_w, off2_b, offb);
    // 5. fea = deform(fea, o2)                         -> bufA
    transpose_w_kernel<<<144, 256>>>(d2_w, wt);
    deform_kernel<<<dg, cb>>>(bufB, offb, wt, d2_b, bufA);
    // 6. o3 = conv(fea)
    conv3x3_kernel<64, 144><<<cg144, cb>>>(bufA, bufA, off3_w, off3_b, offb);
    // 7. fea = deform(supp = neibor, o3)               -> bufB
    transpose_w_kernel<<<144, 256>>>(d3_w, wt);
    deform_kernel<<<dg, cb>>>(neibor, offb, wt, d3_b, bufB);
    // 8. o4 = conv(fea)
    conv3x3_kernel<64, 144><<<cg144, cb>>>(bufB, bufB, off4_w, off4_b, offb);
    // 9. aligned = deform(fea, o4)                     -> d_out
    transpose_w_kernel<<<144, 256>>>(d4_w, wt);
    deform_kernel<<<dg, cb>>>(bufB, offb, wt, d4_b, out);
}